// round 15
// baseline (speedup 1.0000x reference)
#include <cuda_runtime.h>
#include <cuda_bf16.h>
#include <cstdint>

// Problem constants
#define D_MODEL 1024
#define NTOK    8192          // B*L = 8*1024
#define NPAIR   128           // N_HEADS * B = 16*8
#define LSEQ    1024
#define DK      64

// ---------------------------------------------------------------------------
// Scratch (device globals — allocation-free rule)
// ---------------------------------------------------------------------------
__device__ float g_Q[NTOK * D_MODEL];
__device__ float g_K[NTOK * D_MODEL];
__device__ float g_V[NTOK * D_MODEL];
__device__ float g_S[(size_t)NPAIR * LSEQ * LSEQ];   // 512 MB scores

// per-row softmax stats (replaces the 1 GB P round-trip)
__device__ float g_sM[NPAIR * LSEQ];
__device__ float g_sX[NPAIR * LSEQ];
__device__ float g_sI[NPAIR * LSEQ];

// bf16 split pairs
__device__ __nv_bfloat16 g_y0[NTOK * D_MODEL];
__device__ __nv_bfloat16 g_y1[NTOK * D_MODEL];
__device__ __nv_bfloat16 g_c0[NTOK * D_MODEL];       // AV out (split)
__device__ __nv_bfloat16 g_c1[NTOK * D_MODEL];
__device__ __nv_bfloat16 g_v0t[NTOK * D_MODEL];      // per-pair V^T split [64][1024]
__device__ __nv_bfloat16 g_v1t[NTOK * D_MODEL];
__device__ __nv_bfloat16 g_wv0[D_MODEL * D_MODEL];   // W^T splits
__device__ __nv_bfloat16 g_wv1[D_MODEL * D_MODEL];
__device__ __nv_bfloat16 g_wo0[D_MODEL * D_MODEL];
__device__ __nv_bfloat16 g_wo1[D_MODEL * D_MODEL];

// ---------------------------------------------------------------------------
// PTX helpers
// ---------------------------------------------------------------------------
__device__ __forceinline__ uint32_t smem_to_u32(const void* p) {
    uint32_t a;
    asm("{ .reg .u64 t; cvta.to.shared.u64 t, %1; cvt.u32.u64 %0, t; }" : "=r"(a) : "l"(p));
    return a;
}
__device__ __forceinline__ void cp_async16(uint32_t dst, const void* src) {
    asm volatile("cp.async.cg.shared.global [%0], [%1], 16;" :: "r"(dst), "l"(src));
}
#define CP_COMMIT() asm volatile("cp.async.commit_group;" ::: "memory")
#define CP_WAIT(n)  asm volatile("cp.async.wait_group %0;" :: "n"(n) : "memory")

__device__ __forceinline__ void ldmatrix_x4(uint32_t* r, uint32_t addr) {
    asm volatile("ldmatrix.sync.aligned.m8n8.x4.shared.b16 {%0,%1,%2,%3}, [%4];"
                 : "=r"(r[0]), "=r"(r[1]), "=r"(r[2]), "=r"(r[3]) : "r"(addr));
}
__device__ __forceinline__ void mma_bf16(float* d, const uint32_t* a, const uint32_t* b) {
    asm volatile(
        "mma.sync.aligned.m16n8k16.row.col.f32.bf16.bf16.f32 "
        "{%0,%1,%2,%3}, {%4,%5,%6,%7}, {%8,%9}, {%0,%1,%2,%3};"
        : "+f"(d[0]), "+f"(d[1]), "+f"(d[2]), "+f"(d[3])
        : "r"(a[0]), "r"(a[1]), "r"(a[2]), "r"(a[3]), "r"(b[0]), "r"(b[1]));
}

// Packed f32x2 FMA (sm_100+ base ISA): two independent IEEE fma.rn.f32.
__device__ __forceinline__ unsigned long long pack2(float x, float y) {
    unsigned long long r;
    asm("mov.b64 %0, {%1, %2};" : "=l"(r) : "f"(x), "f"(y));
    return r;
}
__device__ __forceinline__ void unpack2(unsigned long long r, float& x, float& y) {
    asm("mov.b64 {%0, %1}, %2;" : "=f"(x), "=f"(y) : "l"(r));
}
__device__ __forceinline__ void fma2p(unsigned long long& d, unsigned long long a,
                                      unsigned long long b) {
    asm("fma.rn.f32x2 %0, %1, %2, %3;" : "=l"(d) : "l"(a), "l"(b), "l"(d));
}

// 2-way bf16 split
__device__ __forceinline__ void bf16_split2(float f, __nv_bfloat16& h0, __nv_bfloat16& h1) {
    h0 = __float2bfloat16(f);
    h1 = __float2bfloat16(f - __bfloat162float(h0));
}

// ---------------------------------------------------------------------------
// [BIT-EXACT, FROZEN — R8 bytes] Q/K projection: C = A@B + bias.
// ---------------------------------------------------------------------------
__global__ __launch_bounds__(256) void sgemm_bias_kernel(
    const float* __restrict__ A, const float* __restrict__ B,
    const float* __restrict__ bias, float* __restrict__ C,
    int M, int N, int K)
{
    __shared__ float As[8][128];
    __shared__ float Bs[8][128];

    const int tid = threadIdx.x;
    const int bm = blockIdx.y * 128;
    const int bn = blockIdx.x * 128;

    const int trow = (tid / 16) * 8;
    const int tcol = (tid % 16) * 8;

    const int arow = tid / 2;
    const int acol = (tid % 2) * 4;
    const int brow = tid / 32;
    const int bcol = (tid % 32) * 4;

    unsigned long long acc2[8][4];
#pragma unroll
    for (int i = 0; i < 8; i++)
#pragma unroll
        for (int j = 0; j < 4; j++) acc2[i][j] = 0ull;

    for (int k0 = 0; k0 < K; k0 += 8) {
        float4 av = *(const float4*)&A[(size_t)(bm + arow) * K + k0 + acol];
        As[acol + 0][arow] = av.x;
        As[acol + 1][arow] = av.y;
        As[acol + 2][arow] = av.z;
        As[acol + 3][arow] = av.w;
        float4 bv = *(const float4*)&B[(size_t)(k0 + brow) * N + bn + bcol];
        *(float4*)&Bs[brow][bcol] = bv;
        __syncthreads();

#pragma unroll
        for (int k = 0; k < 8; k++) {
            float a[8], b[8];
            *(float4*)&a[0] = *(const float4*)&As[k][trow];
            *(float4*)&a[4] = *(const float4*)&As[k][trow + 4];
            *(float4*)&b[0] = *(const float4*)&Bs[k][tcol];
            *(float4*)&b[4] = *(const float4*)&Bs[k][tcol + 4];
            unsigned long long b2[4];
#pragma unroll
            for (int j = 0; j < 4; j++) b2[j] = pack2(b[2 * j], b[2 * j + 1]);
#pragma unroll
            for (int i = 0; i < 8; i++) {
                const unsigned long long a2 = pack2(a[i], a[i]);
#pragma unroll
                for (int j = 0; j < 4; j++) fma2p(acc2[i][j], a2, b2[j]);
            }
        }
        __syncthreads();
    }

    float bb[8];
    *(float4*)&bb[0] = *(const float4*)&bias[bn + tcol];
    *(float4*)&bb[4] = *(const float4*)&bias[bn + tcol + 4];

#pragma unroll
    for (int i = 0; i < 8; i++) {
        float acc[8];
#pragma unroll
        for (int j = 0; j < 4; j++) unpack2(acc2[i][j], acc[2 * j], acc[2 * j + 1]);
        const size_t r = (size_t)(bm + trow + i) * N + bn + tcol;
        float4 o0 = make_float4(acc[0] + bb[0], acc[1] + bb[1],
                                acc[2] + bb[2], acc[3] + bb[3]);
        float4 o1 = make_float4(acc[4] + bb[4], acc[5] + bb[5],
                                acc[6] + bb[6], acc[7] + bb[7]);
        *(float4*)&C[r] = o0;
        *(float4*)&C[r + 4] = o1;
    }
}

// ---------------------------------------------------------------------------
// [BIT-EXACT, FROZEN — R8 bytes] Batched score: S[z] = Q[z]@K[z]^T * (1/32).
// ---------------------------------------------------------------------------
__global__ __launch_bounds__(256) void score_kernel(
    const float* __restrict__ Q, const float* __restrict__ Km,
    float* __restrict__ S)
{
    __shared__ float As[8][128];
    __shared__ float Bs[8][128];

    const int z = blockIdx.z;
    const float* Qz = Q + (size_t)z * LSEQ * DK;
    const float* Kz = Km + (size_t)z * LSEQ * DK;
    float* Sz = S + (size_t)z * LSEQ * LSEQ;

    const int tid = threadIdx.x;
    const int bm = blockIdx.y * 128;
    const int bn = blockIdx.x * 128;
    const int trow = (tid / 16) * 8;
    const int tcol = (tid % 16) * 8;
    const int lrow = tid / 2;
    const int lcol = (tid % 2) * 4;

    unsigned long long acc2[8][4];
#pragma unroll
    for (int i = 0; i < 8; i++)
#pragma unroll
        for (int j = 0; j < 4; j++) acc2[i][j] = 0ull;

    for (int k0 = 0; k0 < DK; k0 += 8) {
        float4 av = *(const float4*)&Qz[(size_t)(bm + lrow) * DK + k0 + lcol];
        As[lcol + 0][lrow] = av.x;
        As[lcol + 1][lrow] = av.y;
        As[lcol + 2][lrow] = av.z;
        As[lcol + 3][lrow] = av.w;
        float4 bv = *(const float4*)&Kz[(size_t)(bn + lrow) * DK + k0 + lcol];
        Bs[lcol + 0][lrow] = bv.x;
        Bs[lcol + 1][lrow] = bv.y;
        Bs[lcol + 2][lrow] = bv.z;
        Bs[lcol + 3][lrow] = bv.w;
        __syncthreads();

#pragma unroll
        for (int k = 0; k < 8; k++) {
            float a[8], b[8];
            *(float4*)&a[0] = *(const float4*)&As[k][trow];
            *(float4*)&a[4] = *(const float4*)&As[k][trow + 4];
            *(float4*)&b[0] = *(const float4*)&Bs[k][tcol];
            *(float4*)&b[4] = *(const float4*)&Bs[k][tcol + 4];
            unsigned long long b2[4];
#pragma unroll
            for (int j = 0; j < 4; j++) b2[j] = pack2(b[2 * j], b[2 * j + 1]);
#pragma unroll
            for (int i = 0; i < 8; i++) {
                const unsigned long long a2 = pack2(a[i], a[i]);
#pragma unroll
                for (int j = 0; j < 4; j++) fma2p(acc2[i][j], a2, b2[j]);
            }
        }
        __syncthreads();
    }

    const float scale = 0.03125f;
#pragma unroll
    for (int i = 0; i < 8; i++) {
        float acc[8];
#pragma unroll
        for (int j = 0; j < 4; j++) unpack2(acc2[i][j], acc[2 * j], acc[2 * j + 1]);
        const size_t r = (size_t)(bm + trow + i) * LSEQ + bn + tcol;
        float4 o0 = make_float4(acc[0] * scale, acc[1] * scale,
                                acc[2] * scale, acc[3] * scale);
        float4 o1 = make_float4(acc[4] * scale, acc[5] * scale,
                                acc[6] * scale, acc[7] * scale);
        *(float4*)&Sz[r] = o0;
        *(float4*)&Sz[r + 4] = o1;
    }
}

// ---------------------------------------------------------------------------
// [BIT-EXACT trees — R8 softmax minus P emission] per-row stats only.
// Writes mean/rowmax/inv (1.5 MB total) instead of 512 MB of P.
// ---------------------------------------------------------------------------
__global__ __launch_bounds__(256) void stats_kernel(
    const float* __restrict__ S, float* __restrict__ gM,
    float* __restrict__ gX, float* __restrict__ gI)
{
    __shared__ float sm[8];
    const size_t row = blockIdx.x;
    const float* r = S + row * LSEQ;
    const int tid = threadIdx.x;

    float4 v = *(const float4*)&r[tid * 4];

    float s = v.x + v.y + v.z + v.w;
#pragma unroll
    for (int o = 16; o > 0; o >>= 1) s += __shfl_xor_sync(0xffffffffu, s, o);
    if ((tid & 31) == 0) sm[tid >> 5] = s;
    __syncthreads();
    if (tid < 32) {
        float t = (tid < 8) ? sm[tid] : 0.f;
#pragma unroll
        for (int o = 4; o > 0; o >>= 1) t += __shfl_xor_sync(0xffffffffu, t, o);
        if (tid == 0) sm[0] = t;
    }
    __syncthreads();
    const float mean = sm[0] * (1.0f / 1024.0f);
    __syncthreads();

    const bool k0 = v.x > mean, k1 = v.y > mean, k2 = v.z > mean, k3 = v.w > mean;
    float m = -3.402823466e38f;
    if (k0) m = v.x;
    if (k1) m = fmaxf(m, v.y);
    if (k2) m = fmaxf(m, v.z);
    if (k3) m = fmaxf(m, v.w);
#pragma unroll
    for (int o = 16; o > 0; o >>= 1) m = fmaxf(m, __shfl_xor_sync(0xffffffffu, m, o));
    if ((tid & 31) == 0) sm[tid >> 5] = m;
    __syncthreads();
    if (tid < 32) {
        float t = (tid < 8) ? sm[tid] : -3.402823466e38f;
#pragma unroll
        for (int o = 4; o > 0; o >>= 1) t = fmaxf(t, __shfl_xor_sync(0xffffffffu, t, o));
        if (tid == 0) sm[0] = t;
    }
    __syncthreads();
    const float rowmax = sm[0];
    __syncthreads();

    float e0 = k0 ? __expf(v.x - rowmax) : 0.f;
    float e1 = k1 ? __expf(v.y - rowmax) : 0.f;
    float e2 = k2 ? __expf(v.z - rowmax) : 0.f;
    float e3 = k3 ? __expf(v.w - rowmax) : 0.f;
    float es = e0 + e1 + e2 + e3;
#pragma unroll
    for (int o = 16; o > 0; o >>= 1) es += __shfl_xor_sync(0xffffffffu, es, o);
    if ((tid & 31) == 0) sm[tid >> 5] = es;
    __syncthreads();
    if (tid < 32) {
        float t = (tid < 8) ? sm[tid] : 0.f;
#pragma unroll
        for (int o = 4; o > 0; o >>= 1) t += __shfl_xor_sync(0xffffffffu, t, o);
        if (tid == 0) sm[0] = t;
    }
    __syncthreads();
    const float inv = 1.0f / sm[0];

    if (tid == 0) {
        gM[row] = mean;
        gX[row] = rowmax;
        gI[row] = inv;
    }
}

// ---------------------------------------------------------------------------
// fp32 -> bf16 (hi, lo) split. n4 = elems/4.
// ---------------------------------------------------------------------------
__global__ __launch_bounds__(256) void split2_kernel(
    const float* __restrict__ in, __nv_bfloat16* __restrict__ o0,
    __nv_bfloat16* __restrict__ o1, int n4)
{
    int i = blockIdx.x * blockDim.x + threadIdx.x;
    if (i >= n4) return;
    float4 v = ((const float4*)in)[i];
    __nv_bfloat16 a0, a1, b0, b1, c0, c1, d0, d1;
    bf16_split2(v.x, a0, a1);
    bf16_split2(v.y, b0, b1);
    bf16_split2(v.z, c0, c1);
    bf16_split2(v.w, d0, d1);
    ((__nv_bfloat162*)o0)[i * 2 + 0] = __nv_bfloat162(a0, b0);
    ((__nv_bfloat162*)o0)[i * 2 + 1] = __nv_bfloat162(c0, d0);
    ((__nv_bfloat162*)o1)[i * 2 + 0] = __nv_bfloat162(a1, b1);
    ((__nv_bfloat162*)o1)[i * 2 + 1] = __nv_bfloat162(c1, d1);
}

// ---------------------------------------------------------------------------
// W [K][N] fp32 -> split bf16 transposed [N][K]
// ---------------------------------------------------------------------------
__global__ __launch_bounds__(256) void split2_transpose_kernel(
    const float* __restrict__ W, __nv_bfloat16* __restrict__ T0,
    __nv_bfloat16* __restrict__ T1)
{
    __shared__ float t[32][33];
    const int x0 = blockIdx.x * 32;
    const int y0 = blockIdx.y * 32;
    const int tx = threadIdx.x;
#pragma unroll
    for (int i = threadIdx.y; i < 32; i += 8)
        t[i][tx] = W[(size_t)(y0 + i) * D_MODEL + x0 + tx];
    __syncthreads();
#pragma unroll
    for (int i = threadIdx.y; i < 32; i += 8) {
        float v = t[tx][i];
        __nv_bfloat16 h0, h1;
        bf16_split2(v, h0, h1);
        size_t o = (size_t)(x0 + i) * D_MODEL + y0 + tx;
        T0[o] = h0;
        T1[o] = h1;
    }
}

// ---------------------------------------------------------------------------
// Batched V^T + split: v{0,1}t[z][d][l] = split(V[z][l][d]).
// ---------------------------------------------------------------------------
__global__ __launch_bounds__(256) void vt_split_kernel(
    const float* __restrict__ V, __nv_bfloat16* __restrict__ T0,
    __nv_bfloat16* __restrict__ T1)
{
    __shared__ float t[32][33];
    const int z = blockIdx.z;
    const float* Vz = V + (size_t)z * LSEQ * DK;
    const int x0 = blockIdx.x * 32;  // d base
    const int y0 = blockIdx.y * 32;  // l base
    const int tx = threadIdx.x;
#pragma unroll
    for (int i = threadIdx.y; i < 32; i += 8)
        t[i][tx] = Vz[(size_t)(y0 + i) * DK + x0 + tx];
    __syncthreads();
#pragma unroll
    for (int i = threadIdx.y; i < 32; i += 8) {
        float v = t[tx][i];
        __nv_bfloat16 h0, h1;
        bf16_split2(v, h0, h1);
        size_t o = (size_t)z * LSEQ * DK + (size_t)(x0 + i) * LSEQ + y0 + tx;
        T0[o] = h0;
        T1[o] = h1;
    }
}

// ---------------------------------------------------------------------------
// bf16x3 GEMM: C = (A0+A1)@(B0+B1)^T + bias  (keeps a0b0, a0b1, a1b0)
// ---------------------------------------------------------------------------
#define ROWB 80
#define MATB (128 * ROWB)               // 10240
#define STAGE3B (4 * MATB)              // 40960 (a0,a1,b0,b1)
#define GEMM3_SMEM_BYTES (2 * STAGE3B)  // 81920

__global__ __launch_bounds__(256) void gemm_bf16x3(
    const __nv_bfloat16* __restrict__ A0, const __nv_bfloat16* __restrict__ A1,
    const __nv_bfloat16* __restrict__ B0, const __nv_bfloat16* __restrict__ B1,
    const float* __restrict__ bias, float* __restrict__ C, int M, int N, int K)
{
    extern __shared__ char smem[];
    const uint32_t sb = smem_to_u32(smem);
    const int tid = threadIdx.x;
    const int lane = tid & 31;
    const int wid = tid >> 5;
    const int wm = wid >> 2;
    const int wn = wid & 3;
    const int bm = blockIdx.y * 128;
    const int bn = blockIdx.x * 128;
    const int nkc = K / 32;

    float d[4][4][4];
#pragma unroll
    for (int i = 0; i < 4; i++)
#pragma unroll
        for (int j = 0; j < 4; j++)
#pragma unroll
            for (int k = 0; k < 4; k++) d[i][j][k] = 0.f;

#define G3_LOAD(stb, k0)                                                      \
    do {                                                                      \
        _Pragma("unroll")                                                     \
        for (int t = 0; t < 2; t++) {                                         \
            const int idx = tid + t * 256;                                    \
            const int row = idx >> 2, ch = idx & 3;                           \
            const uint32_t off = (uint32_t)(row * ROWB + ch * 16);            \
            const size_t ga = (size_t)(bm + row) * K + (k0) + ch * 8;         \
            const size_t gb = (size_t)(bn + row) * K + (k0) + ch * 8;         \
            cp_async16((stb) + 0 * MATB + off, A0 + ga);                      \
            cp_async16((stb) + 1 * MATB + off, A1 + ga);                      \
            cp_async16((stb) + 2 * MATB + off, B0 + gb);                      \
            cp_async16((stb) + 3 * MATB + off, B1 + gb);                      \
        }                                                                     \
    } while (0)

    G3_LOAD(sb, 0);
    CP_COMMIT();
    G3_LOAD(sb + STAGE3B, 32);
    CP_COMMIT();

    const int a_rowsel = lane & 15;
    const uint32_t a_koff = (uint32_t)((lane >> 4) << 4);
    const int b_nsel = (lane & 7) + ((lane >> 4) << 3);
    const uint32_t b_koff = (uint32_t)(((lane >> 3) & 1) << 4);

    for (int kc = 0; kc < nkc; kc++) {
        if (kc + 1 < nkc) { CP_WAIT(1); } else { CP_WAIT(0); }
        __syncthreads();

        const uint32_t st = sb + (kc & 1) * STAGE3B;

#pragma unroll
        for (int ks = 0; ks < 2; ks++) {
            const uint32_t kb = ks * 32;

            uint32_t a0[4][4], a1[4][4];
            uint32_t b0[4][2], b1[4][2];
#pragma unroll
            for (int mt = 0; mt < 4; mt++) {
                const uint32_t ra = (uint32_t)((wm * 64 + mt * 16 + a_rowsel) * ROWB) + kb + a_koff;
                ldmatrix_x4(a0[mt], st + 0 * MATB + ra);
                ldmatrix_x4(a1[mt], st + 1 * MATB + ra);
            }
#pragma unroll
            for (int ntp = 0; ntp < 2; ntp++) {
                const uint32_t rb = (uint32_t)((wn * 32 + ntp * 16 + b_nsel) * ROWB) + kb + b_koff;
                uint32_t t0[4], t1[4];
                ldmatrix_x4(t0, st + 2 * MATB + rb);
                ldmatrix_x4(t1, st + 3 * MATB + rb);
                b0[ntp * 2 + 0][0] = t0[0]; b0[ntp * 2 + 0][1] = t0[1];
                b0[ntp * 2 + 1][0] = t0[2]; b0[ntp * 2 + 1][1] = t0[3];
                b1[ntp * 2 + 0][0] = t1[0]; b1[ntp * 2 + 0][1] = t1[1];
                b1[ntp * 2 + 1][0] = t1[2]; b1[ntp * 2 + 1][1] = t1[3];
            }

#pragma unroll
            for (int mt = 0; mt < 4; mt++)
#pragma unroll
                for (int nt = 0; nt < 4; nt++) {
                    mma_bf16(d[mt][nt], a0[mt], b1[nt]);
                    mma_bf16(d[mt][nt], a1[mt], b0[nt]);
                    mma_bf16(d[mt][nt], a0[mt], b0[nt]);
                }
        }

        __syncthreads();
        if (kc + 2 < nkc) {
            const uint32_t st2 = sb + (kc & 1) * STAGE3B;
            G3_LOAD(st2, (kc + 2) * 32);
        }
        CP_COMMIT();
    }
#undef G3_LOAD

    const int lrow = lane >> 2;
    const int lcol = (lane & 3) * 2;
#pragma unroll
    for (int mt = 0; mt < 4; mt++) {
#pragma unroll
        for (int nt = 0; nt < 4; nt++) {
            const int row = bm + wm * 64 + mt * 16 + lrow;
            const int col = bn + wn * 32 + nt * 8 + lcol;
            const float bb0 = bias[col], bb1 = bias[col + 1];
            float2 v0 = make_float2(d[mt][nt][0] + bb0, d[mt][nt][1] + bb1);
            float2 v1 = make_float2(d[mt][nt][2] + bb0, d[mt][nt][3] + bb1);
            *(float2*)&C[(size_t)row * N + col] = v0;
            *(float2*)&C[(size_t)(row + 8) * N + col] = v1;
        }
    }
}

// ---------------------------------------------------------------------------
// Fused softmax+AV (stats precomputed): O[z] = softmax(mask(S[z])) @ Vt[z]^T.
// Phase-2 of R11 verbatim (validated bit-exact), stats loaded from gmem.
// __launch_bounds__(256, 2): force 2 CTAs/SM (fixes R11's occupancy collapse).
// grid (LSEQ/128, NPAIR), 256 threads.
// ---------------------------------------------------------------------------
#define SBUF_ROWB 144                        // 36 floats per row (conflict pad)
#define AVF_SB (128 * SBUF_ROWB)             // 18432 per S stage
#define AVF_AB (128 * ROWB)                  // 10240 per P-split tile
#define AVF_BB (64 * ROWB)                   // 5120 per V-split tile
#define AVF_S_OFF 0                          // 2 x 18432 = 36864
#define AVF_P_OFF (2 * AVF_SB)               // 36864: 2 stages x (P0,P1)
#define AVF_PST (2 * AVF_AB)                 // 20480 per stage
#define AVF_V_OFF (AVF_P_OFF + 2 * AVF_PST)  // 77824: 2 stages x (V0,V1)
#define AVF_VST (2 * AVF_BB)                 // 10240 per stage
#define AVF_STATM (AVF_V_OFF + 2 * AVF_VST)  // 98304
#define AVF_STATX (AVF_STATM + 512)
#define AVF_STATI (AVF_STATX + 512)
#define AVF_SMEM  (AVF_STATI + 512)          // 99840 -> 2 CTAs/SM fits 228KB

__global__ __launch_bounds__(256, 2) void av_fused2(
    const float* __restrict__ S,
    const float* __restrict__ gM, const float* __restrict__ gX,
    const float* __restrict__ gI,
    const __nv_bfloat16* __restrict__ V0, const __nv_bfloat16* __restrict__ V1,
    __nv_bfloat16* __restrict__ C0, __nv_bfloat16* __restrict__ C1)
{
    extern __shared__ char smem[];
    const uint32_t sb = smem_to_u32(smem);
    const int tid = threadIdx.x;
    const int lane = tid & 31;
    const int wid = tid >> 5;
    const int wm = wid >> 2;
    const int wn = wid & 3;
    const int z = blockIdx.y;
    const int bm = blockIdx.x * 128;
    const float* Sz = S + ((size_t)z * LSEQ + bm) * LSEQ;   // local rows 0..127
    const __nv_bfloat16* V0z = V0 + (size_t)z * LSEQ * DK;
    const __nv_bfloat16* V1z = V1 + (size_t)z * LSEQ * DK;

    float* statM = (float*)(smem + AVF_STATM);
    float* statX = (float*)(smem + AVF_STATX);
    float* statI = (float*)(smem + AVF_STATI);

    // Load per-row stats for this block (128 rows).
    if (tid < 128) {
        const size_t gr = (size_t)z * LSEQ + bm + tid;
        statM[tid] = gM[gr];
        statX[tid] = gX[gr];
        statI[tid] = gI[gr];
    }

    float d[4][2][4];
#pragma unroll
    for (int i = 0; i < 4; i++)
#pragma unroll
        for (int j = 0; j < 2; j++)
#pragma unroll
            for (int k = 0; k < 4; k++) d[i][j][k] = 0.f;

    // Issue S (128x32 fp32) + V (64x32 bf16 pair) tiles for stage kc.
#define AVF_ISSUE(kc)                                                         \
    do {                                                                      \
        const uint32_t sbuf = sb + AVF_S_OFF + ((kc) & 1) * AVF_SB;           \
        _Pragma("unroll")                                                     \
        for (int t = 0; t < 4; t++) {                                         \
            const int idx = tid + t * 256;                                    \
            const int row = idx >> 3, ch = idx & 7;                           \
            cp_async16(sbuf + (uint32_t)(row * SBUF_ROWB + ch * 16),          \
                       Sz + (size_t)row * LSEQ + (kc) * 32 + ch * 4);         \
        }                                                                     \
        const uint32_t vb = sb + AVF_V_OFF + ((kc) & 1) * AVF_VST;            \
        const int vrow = tid >> 2, chv = tid & 3;                             \
        if (vrow < 64) {                                                      \
            const uint32_t off = (uint32_t)(vrow * ROWB + chv * 16);          \
            const size_t gb = (size_t)vrow * LSEQ + (kc) * 32 + chv * 8;      \
            cp_async16(vb + off, V0z + gb);                                   \
            cp_async16(vb + AVF_BB + off, V1z + gb);                          \
        }                                                                     \
    } while (0)

    // Convert S tile (smem fp32) -> P tile (smem bf16 pair), inline softmax.
#define AVF_CONVERT(kc)                                                       \
    do {                                                                      \
        const char* sbuf = smem + AVF_S_OFF + ((kc) & 1) * AVF_SB;            \
        char* pb = smem + AVF_P_OFF + ((kc) & 1) * AVF_PST;                   \
        _Pragma("unroll")                                                     \
        for (int t = 0; t < 4; t++) {                                         \
            const int idx = tid + t * 256;                                    \
            const int row = idx >> 3, ch = idx & 7;                           \
            float4 sv = *(const float4*)(sbuf + row * SBUF_ROWB + ch * 16);   \
            const float mu = statM[row], mx = statX[row], iv = statI[row];    \
            float svv[4] = {sv.x, sv.y, sv.z, sv.w};                          \
            __nv_bfloat16 h0[4], h1[4];                                       \
            _Pragma("unroll")                                                 \
            for (int j = 0; j < 4; j++) {                                     \
                float e = (svv[j] > mu) ? __expf(svv[j] - mx) : 0.f;          \
                float p = e * iv;                                             \
                bf16_split2(p, h0[j], h1[j]);                                 \
            }                                                                 \
            __nv_bfloat162* p0p = (__nv_bfloat162*)(pb + row * ROWB + ch * 8);\
            __nv_bfloat162* p1p = (__nv_bfloat162*)(pb + AVF_AB + row * ROWB + ch * 8);\
            p0p[0] = __nv_bfloat162(h0[0], h0[1]);                            \
            p0p[1] = __nv_bfloat162(h0[2], h0[3]);                            \
            p1p[0] = __nv_bfloat162(h1[0], h1[1]);                            \
            p1p[1] = __nv_bfloat162(h1[2], h1[3]);                            \
        }                                                                     \
    } while (0)

    // Prologue: stages 0,1 in flight; convert P(0).
    AVF_ISSUE(0); CP_COMMIT();
    AVF_ISSUE(1); CP_COMMIT();
    CP_WAIT(1);
    __syncthreads();       // S(0) + stats visible
    AVF_CONVERT(0);
    __syncthreads();       // P(0) visible

    const int a_rowsel = lane & 15;
    const uint32_t a_koff = (uint32_t)((lane >> 4) << 4);
    const int b_nsel = (lane & 7) + ((lane >> 4) << 3);
    const uint32_t b_koff = (uint32_t)(((lane >> 3) & 1) << 4);

    const int nkc = LSEQ / 32;   // 32
    for (int kc = 0; kc < nkc; kc++) {
        const uint32_t ast = sb + AVF_P_OFF + (kc & 1) * AVF_PST;
        const uint32_t vst = sb + AVF_V_OFF + (kc & 1) * AVF_VST;

#pragma unroll
        for (int ks = 0; ks < 2; ks++) {
            const uint32_t kb = ks * 32;

            uint32_t a0[4][4], a1[4][4];
#pragma unroll
            for (int mt = 0; mt < 4; mt++) {
                const uint32_t ra = (uint32_t)((wm * 64 + mt * 16 + a_rowsel) * ROWB) + kb + a_koff;
                ldmatrix_x4(a0[mt], ast + ra);
                ldmatrix_x4(a1[mt], ast + AVF_AB + ra);
            }
            uint32_t b0[2][2], b1[2][2];
            {
                const uint32_t rb = (uint32_t)((wn * 16 + b_nsel) * ROWB) + kb + b_koff;
                uint32_t t0[4], t1[4];
                ldmatrix_x4(t0, vst + rb);
                ldmatrix_x4(t1, vst + AVF_BB + rb);
                b0[0][0] = t0[0]; b0[0][1] = t0[1];
                b0[1][0] = t0[2]; b0[1][1] = t0[3];
                b1[0][0] = t1[0]; b1[0][1] = t1[1];
                b1[1][0] = t1[2]; b1[1][1] = t1[3];
            }

#pragma unroll
            for (int mt = 0; mt < 4; mt++)
#pragma unroll
                for (int nt = 0; nt < 2; nt++) {
                    mma_bf16(d[mt][nt], a0[mt], b1[nt]);
                    mma_bf16(d[mt][nt], a1[mt], b0[nt]);
                    mma_bf16(d[mt][nt], a0[mt], b0[nt]);
                }
        }

        __syncthreads();   // readers done with P(kc)/V(kc)/S-slot(kc)
        if (kc + 2 < nkc) { AVF_ISSUE(kc + 2); CP_COMMIT(); }
        if (kc + 1 < nkc) {
            if (kc + 2 < nkc) { CP_WAIT(1); } else { CP_WAIT(0); }
            __syncthreads();          // S(kc+1)/V(kc+1) visible
            AVF_CONVERT(kc + 1);
            __syncthreads();          // P(kc+1) visible for next mma
        }
    }
#undef AVF_ISSUE
#undef AVF_CONVERT

    const int lrow = lane >> 2;
    const int lcol = (lane & 3) * 2;
#pragma unroll
    for (int mt = 0; mt < 4; mt++) {
#pragma unroll
        for (int nt = 0; nt < 2; nt++) {
            const int row = bm + wm * 64 + mt * 16 + lrow;
            const int col = wn * 16 + nt * 8 + lcol;
            const size_t o0 = (size_t)z * LSEQ * DK + (size_t)row * DK + col;
            const size_t o1 = (size_t)z * LSEQ * DK + (size_t)(row + 8) * DK + col;
            __nv_bfloat16 h0, h1, g0, g1;
            bf16_split2(d[mt][nt][0], h0, h1);
            bf16_split2(d[mt][nt][1], g0, g1);
            *(__nv_bfloat162*)&C0[o0] = __nv_bfloat162(h0, g0);
            *(__nv_bfloat162*)&C1[o0] = __nv_bfloat162(h1, g1);
            bf16_split2(d[mt][nt][2], h0, h1);
            bf16_split2(d[mt][nt][3], g0, g1);
            *(__nv_bfloat162*)&C0[o1] = __nv_bfloat162(h0, g0);
            *(__nv_bfloat162*)&C1[o1] = __nv_bfloat162(h1, g1);
        }
    }
}

// ---------------------------------------------------------------------------
// Launch: R8 structure; softmax -> stats_kernel; AV -> av_fused2.
// ---------------------------------------------------------------------------
extern "C" void kernel_launch(void* const* d_in, const int* in_sizes, int n_in,
                              void* d_out, int out_size)
{
    const float* x  = (const float*)d_in[0];
    const float* y  = (const float*)d_in[1];
    const float* Wq = (const float*)d_in[2];
    const float* bq = (const float*)d_in[3];
    const float* Wk = (const float*)d_in[4];
    const float* bk = (const float*)d_in[5];
    const float* Wv = (const float*)d_in[6];
    const float* bv = (const float*)d_in[7];
    const float* Wo = (const float*)d_in[8];
    const float* bo = (const float*)d_in[9];
    float* out = (float*)d_out;

    float *gQ, *gK, *gV, *gS, *gM, *gX, *gI;
    cudaGetSymbolAddress((void**)&gQ, g_Q);
    cudaGetSymbolAddress((void**)&gK, g_K);
    cudaGetSymbolAddress((void**)&gV, g_V);
    cudaGetSymbolAddress((void**)&gS, g_S);
    cudaGetSymbolAddress((void**)&gM, g_sM);
    cudaGetSymbolAddress((void**)&gX, g_sX);
    cudaGetSymbolAddress((void**)&gI, g_sI);
    __nv_bfloat16 *y0, *y1, *c0, *c1, *v0t, *v1t;
    __nv_bfloat16 *wv0, *wv1, *wo0, *wo1;
    cudaGetSymbolAddress((void**)&y0, g_y0);
    cudaGetSymbolAddress((void**)&y1, g_y1);
    cudaGetSymbolAddress((void**)&c0, g_c0);
    cudaGetSymbolAddress((void**)&c1, g_c1);
    cudaGetSymbolAddress((void**)&v0t, g_v0t);
    cudaGetSymbolAddress((void**)&v1t, g_v1t);
    cudaGetSymbolAddress((void**)&wv0, g_wv0);
    cudaGetSymbolAddress((void**)&wv1, g_wv1);
    cudaGetSymbolAddress((void**)&wo0, g_wo0);
    cudaGetSymbolAddress((void**)&wo1, g_wo1);

    cudaFuncSetAttribute(gemm_bf16x3, cudaFuncAttributeMaxDynamicSharedMemorySize,
                         GEMM3_SMEM_BYTES);
    cudaFuncSetAttribute(av_fused2, cudaFuncAttributeMaxDynamicSharedMemorySize,
                         AVF_SMEM);

    cudaEvent_t eFork, eK, eB;
    cudaEventCreateWithFlags(&eFork, cudaEventDisableTiming);
    cudaEventCreateWithFlags(&eK, cudaEventDisableTiming);
    cudaEventCreateWithFlags(&eB, cudaEventDisableTiming);

    const cudaStream_t sMain = 0;                   // legacy default stream
    const cudaStream_t sSide = cudaStreamPerThread; // second lane, no creation

    dim3 tt(32, 8);
    dim3 tg(32, 32);
    dim3 gGemm(D_MODEL / 128, NTOK / 128);  // (8, 64)
    dim3 gScore(LSEQ / 128, LSEQ / 128, NPAIR);
    dim3 gVtG(DK / 32, LSEQ / 32, NPAIR);
    dim3 gAV(LSEQ / 128, NPAIR);
    const int n4 = NTOK * D_MODEL / 4;

    // Fork side lane off the main stream.
    cudaEventRecord(eFork, sMain);
    cudaStreamWaitEvent(sSide, eFork, 0);

    // Side lane: K projection (bit-exact), then the tensor-prep chain.
    sgemm_bias_kernel<<<gGemm, 256, 0, sSide>>>(y, Wk, bk, gK, NTOK, D_MODEL, D_MODEL);
    cudaEventRecord(eK, sSide);
    split2_kernel<<<(n4 + 255) / 256, 256, 0, sSide>>>(y, y0, y1, n4);
    split2_transpose_kernel<<<tg, tt, 0, sSide>>>(Wv, wv0, wv1);
    split2_transpose_kernel<<<tg, tt, 0, sSide>>>(Wo, wo0, wo1);
    gemm_bf16x3<<<gGemm, 256, GEMM3_SMEM_BYTES, sSide>>>(y0, y1, wv0, wv1, bv, gV,
                                                         NTOK, D_MODEL, D_MODEL);
    vt_split_kernel<<<gVtG, tt, 0, sSide>>>(gV, v0t, v1t);
    cudaEventRecord(eB, sSide);

    // Main lane: Q projection runs concurrently with the side lane.
    sgemm_bias_kernel<<<gGemm, 256, 0, sMain>>>(x, Wq, bq, gQ, NTOK, D_MODEL, D_MODEL);

    // Join 1: score needs both Q (main) and K (side).
    cudaStreamWaitEvent(sMain, eK, 0);
    score_kernel<<<gScore, 256, 0, sMain>>>(gQ, gK, gS);

    // Row stats (bit-exact trees; tiny output instead of 512 MB P).
    stats_kernel<<<(unsigned)(NPAIR * LSEQ), 256, 0, sMain>>>(gS, gM, gX, gI);

    // Join 2: fused softmax+AV needs stats (main) and split V^T (side).
    cudaStreamWaitEvent(sMain, eB, 0);
    av_fused2<<<gAV, 256, AVF_SMEM, sMain>>>(gS, gM, gX, gI, v0t, v1t, c0, c1);

    gemm_bf16x3<<<gGemm, 256, GEMM3_SMEM_BYTES, sMain>>>(c0, c1, wo0, wo1, bo, out,
                                                         NTOK, D_MODEL, D_MODEL);
}

// round 17
// speedup vs baseline: 1.0596x; 1.0596x over previous
#include <cuda_runtime.h>
#include <cuda_bf16.h>
#include <cuda_fp16.h>
#include <cstdint>

// Problem constants
#define D_MODEL 1024
#define NTOK    8192          // B*L = 8*1024
#define NPAIR   128           // N_HEADS * B = 16*8
#define LSEQ    1024
#define DK      64

// ---------------------------------------------------------------------------
// Scratch (device globals — allocation-free rule)
// ---------------------------------------------------------------------------
__device__ float g_Q[NTOK * D_MODEL];
__device__ float g_K[NTOK * D_MODEL];
__device__ float g_V[NTOK * D_MODEL];
__device__ float g_S[(size_t)NPAIR * LSEQ * LSEQ];   // 512 MB scores

// bf16 buffers (projection paths)
__device__ __nv_bfloat16 g_y0[NTOK * D_MODEL];
__device__ __nv_bfloat16 g_y1[NTOK * D_MODEL];
__device__ __nv_bfloat16 g_c0[NTOK * D_MODEL];       // AV out (split)
__device__ __nv_bfloat16 g_c1[NTOK * D_MODEL];
__device__ __nv_bfloat16 g_wv0[D_MODEL * D_MODEL];   // W^T splits
__device__ __nv_bfloat16 g_wv1[D_MODEL * D_MODEL];
__device__ __nv_bfloat16 g_wo0[D_MODEL * D_MODEL];
__device__ __nv_bfloat16 g_wo1[D_MODEL * D_MODEL];

// fp16 buffers (attention AV path: P single, V^T split)
__device__ __half g_P[(size_t)NPAIR * LSEQ * LSEQ];  // 256 MB
__device__ __half g_v0t[NTOK * D_MODEL];
__device__ __half g_v1t[NTOK * D_MODEL];

// ---------------------------------------------------------------------------
// PTX helpers
// ---------------------------------------------------------------------------
__device__ __forceinline__ uint32_t smem_to_u32(const void* p) {
    uint32_t a;
    asm("{ .reg .u64 t; cvta.to.shared.u64 t, %1; cvt.u32.u64 %0, t; }" : "=r"(a) : "l"(p));
    return a;
}
__device__ __forceinline__ void cp_async16(uint32_t dst, const void* src) {
    asm volatile("cp.async.cg.shared.global [%0], [%1], 16;" :: "r"(dst), "l"(src));
}
#define CP_COMMIT() asm volatile("cp.async.commit_group;" ::: "memory")
#define CP_WAIT(n)  asm volatile("cp.async.wait_group %0;" :: "n"(n) : "memory")

__device__ __forceinline__ void ldmatrix_x4(uint32_t* r, uint32_t addr) {
    asm volatile("ldmatrix.sync.aligned.m8n8.x4.shared.b16 {%0,%1,%2,%3}, [%4];"
                 : "=r"(r[0]), "=r"(r[1]), "=r"(r[2]), "=r"(r[3]) : "r"(addr));
}
__device__ __forceinline__ void mma_bf16(float* d, const uint32_t* a, const uint32_t* b) {
    asm volatile(
        "mma.sync.aligned.m16n8k16.row.col.f32.bf16.bf16.f32 "
        "{%0,%1,%2,%3}, {%4,%5,%6,%7}, {%8,%9}, {%0,%1,%2,%3};"
        : "+f"(d[0]), "+f"(d[1]), "+f"(d[2]), "+f"(d[3])
        : "r"(a[0]), "r"(a[1]), "r"(a[2]), "r"(a[3]), "r"(b[0]), "r"(b[1]));
}
__device__ __forceinline__ void mma_f16(float* d, const uint32_t* a, const uint32_t* b) {
    asm volatile(
        "mma.sync.aligned.m16n8k16.row.col.f32.f16.f16.f32 "
        "{%0,%1,%2,%3}, {%4,%5,%6,%7}, {%8,%9}, {%0,%1,%2,%3};"
        : "+f"(d[0]), "+f"(d[1]), "+f"(d[2]), "+f"(d[3])
        : "r"(a[0]), "r"(a[1]), "r"(a[2]), "r"(a[3]), "r"(b[0]), "r"(b[1]));
}

// Packed f32x2 FMA (sm_100+ base ISA): two independent IEEE fma.rn.f32.
__device__ __forceinline__ unsigned long long pack2(float x, float y) {
    unsigned long long r;
    asm("mov.b64 %0, {%1, %2};" : "=l"(r) : "f"(x), "f"(y));
    return r;
}
__device__ __forceinline__ void unpack2(unsigned long long r, float& x, float& y) {
    asm("mov.b64 {%0, %1}, %2;" : "=f"(x), "=f"(y) : "l"(r));
}
__device__ __forceinline__ void fma2p(unsigned long long& d, unsigned long long a,
                                      unsigned long long b) {
    asm("fma.rn.f32x2 %0, %1, %2, %3;" : "=l"(d) : "l"(a), "l"(b), "l"(d));
}

// 2-way bf16 split
__device__ __forceinline__ void bf16_split2(float f, __nv_bfloat16& h0, __nv_bfloat16& h1) {
    h0 = __float2bfloat16(f);
    h1 = __float2bfloat16(f - __bfloat162float(h0));
}
// 2-way fp16 split
__device__ __forceinline__ void f16_split2(float f, __half& h0, __half& h1) {
    h0 = __float2half(f);
    h1 = __float2half(f - __half2float(h0));
}

// ---------------------------------------------------------------------------
// [BIT-EXACT, FROZEN — R8 bytes] Q/K projection: C = A@B + bias.
// ---------------------------------------------------------------------------
__global__ __launch_bounds__(256) void sgemm_bias_kernel(
    const float* __restrict__ A, const float* __restrict__ B,
    const float* __restrict__ bias, float* __restrict__ C,
    int M, int N, int K)
{
    __shared__ float As[8][128];
    __shared__ float Bs[8][128];

    const int tid = threadIdx.x;
    const int bm = blockIdx.y * 128;
    const int bn = blockIdx.x * 128;

    const int trow = (tid / 16) * 8;
    const int tcol = (tid % 16) * 8;

    const int arow = tid / 2;
    const int acol = (tid % 2) * 4;
    const int brow = tid / 32;
    const int bcol = (tid % 32) * 4;

    unsigned long long acc2[8][4];
#pragma unroll
    for (int i = 0; i < 8; i++)
#pragma unroll
        for (int j = 0; j < 4; j++) acc2[i][j] = 0ull;

    for (int k0 = 0; k0 < K; k0 += 8) {
        float4 av = *(const float4*)&A[(size_t)(bm + arow) * K + k0 + acol];
        As[acol + 0][arow] = av.x;
        As[acol + 1][arow] = av.y;
        As[acol + 2][arow] = av.z;
        As[acol + 3][arow] = av.w;
        float4 bv = *(const float4*)&B[(size_t)(k0 + brow) * N + bn + bcol];
        *(float4*)&Bs[brow][bcol] = bv;
        __syncthreads();

#pragma unroll
        for (int k = 0; k < 8; k++) {
            float a[8], b[8];
            *(float4*)&a[0] = *(const float4*)&As[k][trow];
            *(float4*)&a[4] = *(const float4*)&As[k][trow + 4];
            *(float4*)&b[0] = *(const float4*)&Bs[k][tcol];
            *(float4*)&b[4] = *(const float4*)&Bs[k][tcol + 4];
            unsigned long long b2[4];
#pragma unroll
            for (int j = 0; j < 4; j++) b2[j] = pack2(b[2 * j], b[2 * j + 1]);
#pragma unroll
            for (int i = 0; i < 8; i++) {
                const unsigned long long a2 = pack2(a[i], a[i]);
#pragma unroll
                for (int j = 0; j < 4; j++) fma2p(acc2[i][j], a2, b2[j]);
            }
        }
        __syncthreads();
    }

    float bb[8];
    *(float4*)&bb[0] = *(const float4*)&bias[bn + tcol];
    *(float4*)&bb[4] = *(const float4*)&bias[bn + tcol + 4];

#pragma unroll
    for (int i = 0; i < 8; i++) {
        float acc[8];
#pragma unroll
        for (int j = 0; j < 4; j++) unpack2(acc2[i][j], acc[2 * j], acc[2 * j + 1]);
        const size_t r = (size_t)(bm + trow + i) * N + bn + tcol;
        float4 o0 = make_float4(acc[0] + bb[0], acc[1] + bb[1],
                                acc[2] + bb[2], acc[3] + bb[3]);
        float4 o1 = make_float4(acc[4] + bb[4], acc[5] + bb[5],
                                acc[6] + bb[6], acc[7] + bb[7]);
        *(float4*)&C[r] = o0;
        *(float4*)&C[r + 4] = o1;
    }
}

// ---------------------------------------------------------------------------
// [BIT-EXACT, FROZEN — R8 bytes] Batched score: S[z] = Q[z]@K[z]^T * (1/32).
// ---------------------------------------------------------------------------
__global__ __launch_bounds__(256) void score_kernel(
    const float* __restrict__ Q, const float* __restrict__ Km,
    float* __restrict__ S)
{
    __shared__ float As[8][128];
    __shared__ float Bs[8][128];

    const int z = blockIdx.z;
    const float* Qz = Q + (size_t)z * LSEQ * DK;
    const float* Kz = Km + (size_t)z * LSEQ * DK;
    float* Sz = S + (size_t)z * LSEQ * LSEQ;

    const int tid = threadIdx.x;
    const int bm = blockIdx.y * 128;
    const int bn = blockIdx.x * 128;
    const int trow = (tid / 16) * 8;
    const int tcol = (tid % 16) * 8;
    const int lrow = tid / 2;
    const int lcol = (tid % 2) * 4;

    unsigned long long acc2[8][4];
#pragma unroll
    for (int i = 0; i < 8; i++)
#pragma unroll
        for (int j = 0; j < 4; j++) acc2[i][j] = 0ull;

    for (int k0 = 0; k0 < DK; k0 += 8) {
        float4 av = *(const float4*)&Qz[(size_t)(bm + lrow) * DK + k0 + lcol];
        As[lcol + 0][lrow] = av.x;
        As[lcol + 1][lrow] = av.y;
        As[lcol + 2][lrow] = av.z;
        As[lcol + 3][lrow] = av.w;
        float4 bv = *(const float4*)&Kz[(size_t)(bn + lrow) * DK + k0 + lcol];
        Bs[lcol + 0][lrow] = bv.x;
        Bs[lcol + 1][lrow] = bv.y;
        Bs[lcol + 2][lrow] = bv.z;
        Bs[lcol + 3][lrow] = bv.w;
        __syncthreads();

#pragma unroll
        for (int k = 0; k < 8; k++) {
            float a[8], b[8];
            *(float4*)&a[0] = *(const float4*)&As[k][trow];
            *(float4*)&a[4] = *(const float4*)&As[k][trow + 4];
            *(float4*)&b[0] = *(const float4*)&Bs[k][tcol];
            *(float4*)&b[4] = *(const float4*)&Bs[k][tcol + 4];
            unsigned long long b2[4];
#pragma unroll
            for (int j = 0; j < 4; j++) b2[j] = pack2(b[2 * j], b[2 * j + 1]);
#pragma unroll
            for (int i = 0; i < 8; i++) {
                const unsigned long long a2 = pack2(a[i], a[i]);
#pragma unroll
                for (int j = 0; j < 4; j++) fma2p(acc2[i][j], a2, b2[j]);
            }
        }
        __syncthreads();
    }

    const float scale = 0.03125f;
#pragma unroll
    for (int i = 0; i < 8; i++) {
        float acc[8];
#pragma unroll
        for (int j = 0; j < 4; j++) unpack2(acc2[i][j], acc[2 * j], acc[2 * j + 1]);
        const size_t r = (size_t)(bm + trow + i) * LSEQ + bn + tcol;
        float4 o0 = make_float4(acc[0] * scale, acc[1] * scale,
                                acc[2] * scale, acc[3] * scale);
        float4 o1 = make_float4(acc[4] * scale, acc[5] * scale,
                                acc[6] * scale, acc[7] * scale);
        *(float4*)&Sz[r] = o0;
        *(float4*)&Sz[r + 4] = o1;
    }
}

// ---------------------------------------------------------------------------
// [BIT-EXACT mask math — R8 trees] mean -> mask -> softmax; emits P as
// SINGLE fp16 (RN, 2^-11 rounding). Linear-path error only.
// ---------------------------------------------------------------------------
__global__ __launch_bounds__(256) void softmax_kernel(
    const float* __restrict__ S, __half* __restrict__ P)
{
    __shared__ float sm[8];
    const size_t row = blockIdx.x;
    const float* r = S + row * LSEQ;
    const int tid = threadIdx.x;

    float4 v = *(const float4*)&r[tid * 4];

    float s = v.x + v.y + v.z + v.w;
#pragma unroll
    for (int o = 16; o > 0; o >>= 1) s += __shfl_xor_sync(0xffffffffu, s, o);
    if ((tid & 31) == 0) sm[tid >> 5] = s;
    __syncthreads();
    if (tid < 32) {
        float t = (tid < 8) ? sm[tid] : 0.f;
#pragma unroll
        for (int o = 4; o > 0; o >>= 1) t += __shfl_xor_sync(0xffffffffu, t, o);
        if (tid == 0) sm[0] = t;
    }
    __syncthreads();
    const float mean = sm[0] * (1.0f / 1024.0f);
    __syncthreads();

    const bool k0 = v.x > mean, k1 = v.y > mean, k2 = v.z > mean, k3 = v.w > mean;
    float m = -3.402823466e38f;
    if (k0) m = v.x;
    if (k1) m = fmaxf(m, v.y);
    if (k2) m = fmaxf(m, v.z);
    if (k3) m = fmaxf(m, v.w);
#pragma unroll
    for (int o = 16; o > 0; o >>= 1) m = fmaxf(m, __shfl_xor_sync(0xffffffffu, m, o));
    if ((tid & 31) == 0) sm[tid >> 5] = m;
    __syncthreads();
    if (tid < 32) {
        float t = (tid < 8) ? sm[tid] : -3.402823466e38f;
#pragma unroll
        for (int o = 4; o > 0; o >>= 1) t = fmaxf(t, __shfl_xor_sync(0xffffffffu, t, o));
        if (tid == 0) sm[0] = t;
    }
    __syncthreads();
    const float rowmax = sm[0];
    __syncthreads();

    float e0 = k0 ? __expf(v.x - rowmax) : 0.f;
    float e1 = k1 ? __expf(v.y - rowmax) : 0.f;
    float e2 = k2 ? __expf(v.z - rowmax) : 0.f;
    float e3 = k3 ? __expf(v.w - rowmax) : 0.f;
    float es = e0 + e1 + e2 + e3;
#pragma unroll
    for (int o = 16; o > 0; o >>= 1) es += __shfl_xor_sync(0xffffffffu, es, o);
    if ((tid & 31) == 0) sm[tid >> 5] = es;
    __syncthreads();
    if (tid < 32) {
        float t = (tid < 8) ? sm[tid] : 0.f;
#pragma unroll
        for (int o = 4; o > 0; o >>= 1) t += __shfl_xor_sync(0xffffffffu, t, o);
        if (tid == 0) sm[0] = t;
    }
    __syncthreads();
    const float inv = 1.0f / sm[0];

    const size_t o4 = row * LSEQ + tid * 4;
    *(__half2*)&P[o4 + 0] = __halves2half2(__float2half(e0 * inv), __float2half(e1 * inv));
    *(__half2*)&P[o4 + 2] = __halves2half2(__float2half(e2 * inv), __float2half(e3 * inv));
}

// ---------------------------------------------------------------------------
// fp32 -> bf16 (hi, lo) split. n4 = elems/4.
// ---------------------------------------------------------------------------
__global__ __launch_bounds__(256) void split2_kernel(
    const float* __restrict__ in, __nv_bfloat16* __restrict__ o0,
    __nv_bfloat16* __restrict__ o1, int n4)
{
    int i = blockIdx.x * blockDim.x + threadIdx.x;
    if (i >= n4) return;
    float4 v = ((const float4*)in)[i];
    __nv_bfloat16 a0, a1, b0, b1, c0, c1, d0, d1;
    bf16_split2(v.x, a0, a1);
    bf16_split2(v.y, b0, b1);
    bf16_split2(v.z, c0, c1);
    bf16_split2(v.w, d0, d1);
    ((__nv_bfloat162*)o0)[i * 2 + 0] = __nv_bfloat162(a0, b0);
    ((__nv_bfloat162*)o0)[i * 2 + 1] = __nv_bfloat162(c0, d0);
    ((__nv_bfloat162*)o1)[i * 2 + 0] = __nv_bfloat162(a1, b1);
    ((__nv_bfloat162*)o1)[i * 2 + 1] = __nv_bfloat162(c1, d1);
}

// ---------------------------------------------------------------------------
// W [K][N] fp32 -> split bf16 transposed [N][K]
// ---------------------------------------------------------------------------
__global__ __launch_bounds__(256) void split2_transpose_kernel(
    const float* __restrict__ W, __nv_bfloat16* __restrict__ T0,
    __nv_bfloat16* __restrict__ T1)
{
    __shared__ float t[32][33];
    const int x0 = blockIdx.x * 32;
    const int y0 = blockIdx.y * 32;
    const int tx = threadIdx.x;
#pragma unroll
    for (int i = threadIdx.y; i < 32; i += 8)
        t[i][tx] = W[(size_t)(y0 + i) * D_MODEL + x0 + tx];
    __syncthreads();
#pragma unroll
    for (int i = threadIdx.y; i < 32; i += 8) {
        float v = t[tx][i];
        __nv_bfloat16 h0, h1;
        bf16_split2(v, h0, h1);
        size_t o = (size_t)(x0 + i) * D_MODEL + y0 + tx;
        T0[o] = h0;
        T1[o] = h1;
    }
}

// ---------------------------------------------------------------------------
// Batched V^T + fp16 split: v{0,1}t[z][d][l] = f16split(V[z][l][d]).
// ---------------------------------------------------------------------------
__global__ __launch_bounds__(256) void vt_split_kernel(
    const float* __restrict__ V, __half* __restrict__ T0,
    __half* __restrict__ T1)
{
    __shared__ float t[32][33];
    const int z = blockIdx.z;
    const float* Vz = V + (size_t)z * LSEQ * DK;
    const int x0 = blockIdx.x * 32;  // d base
    const int y0 = blockIdx.y * 32;  // l base
    const int tx = threadIdx.x;
#pragma unroll
    for (int i = threadIdx.y; i < 32; i += 8)
        t[i][tx] = Vz[(size_t)(y0 + i) * DK + x0 + tx];
    __syncthreads();
#pragma unroll
    for (int i = threadIdx.y; i < 32; i += 8) {
        float v = t[tx][i];
        __half h0, h1;
        f16_split2(v, h0, h1);
        size_t o = (size_t)z * LSEQ * DK + (size_t)(x0 + i) * LSEQ + y0 + tx;
        T0[o] = h0;
        T1[o] = h1;
    }
}

// ---------------------------------------------------------------------------
// bf16x3 GEMM: C = (A0+A1)@(B0+B1)^T + bias  (keeps a0b0, a0b1, a1b0)
// ---------------------------------------------------------------------------
#define ROWB 80
#define MATB (128 * ROWB)               // 10240
#define STAGE3B (4 * MATB)              // 40960 (a0,a1,b0,b1)
#define GEMM3_SMEM_BYTES (2 * STAGE3B)  // 81920

__global__ __launch_bounds__(256) void gemm_bf16x3(
    const __nv_bfloat16* __restrict__ A0, const __nv_bfloat16* __restrict__ A1,
    const __nv_bfloat16* __restrict__ B0, const __nv_bfloat16* __restrict__ B1,
    const float* __restrict__ bias, float* __restrict__ C, int M, int N, int K)
{
    extern __shared__ char smem[];
    const uint32_t sb = smem_to_u32(smem);
    const int tid = threadIdx.x;
    const int lane = tid & 31;
    const int wid = tid >> 5;
    const int wm = wid >> 2;
    const int wn = wid & 3;
    const int bm = blockIdx.y * 128;
    const int bn = blockIdx.x * 128;
    const int nkc = K / 32;

    float d[4][4][4];
#pragma unroll
    for (int i = 0; i < 4; i++)
#pragma unroll
        for (int j = 0; j < 4; j++)
#pragma unroll
            for (int k = 0; k < 4; k++) d[i][j][k] = 0.f;

#define G3_LOAD(stb, k0)                                                      \
    do {                                                                      \
        _Pragma("unroll")                                                     \
        for (int t = 0; t < 2; t++) {                                         \
            const int idx = tid + t * 256;                                    \
            const int row = idx >> 2, ch = idx & 3;                           \
            const uint32_t off = (uint32_t)(row * ROWB + ch * 16);            \
            const size_t ga = (size_t)(bm + row) * K + (k0) + ch * 8;         \
            const size_t gb = (size_t)(bn + row) * K + (k0) + ch * 8;         \
            cp_async16((stb) + 0 * MATB + off, A0 + ga);                      \
            cp_async16((stb) + 1 * MATB + off, A1 + ga);                      \
            cp_async16((stb) + 2 * MATB + off, B0 + gb);                      \
            cp_async16((stb) + 3 * MATB + off, B1 + gb);                      \
        }                                                                     \
    } while (0)

    G3_LOAD(sb, 0);
    CP_COMMIT();
    G3_LOAD(sb + STAGE3B, 32);
    CP_COMMIT();

    const int a_rowsel = lane & 15;
    const uint32_t a_koff = (uint32_t)((lane >> 4) << 4);
    const int b_nsel = (lane & 7) + ((lane >> 4) << 3);
    const uint32_t b_koff = (uint32_t)(((lane >> 3) & 1) << 4);

    for (int kc = 0; kc < nkc; kc++) {
        if (kc + 1 < nkc) { CP_WAIT(1); } else { CP_WAIT(0); }
        __syncthreads();

        const uint32_t st = sb + (kc & 1) * STAGE3B;

#pragma unroll
        for (int ks = 0; ks < 2; ks++) {
            const uint32_t kb = ks * 32;

            uint32_t a0[4][4], a1[4][4];
            uint32_t b0[4][2], b1[4][2];
#pragma unroll
            for (int mt = 0; mt < 4; mt++) {
                const uint32_t ra = (uint32_t)((wm * 64 + mt * 16 + a_rowsel) * ROWB) + kb + a_koff;
                ldmatrix_x4(a0[mt], st + 0 * MATB + ra);
                ldmatrix_x4(a1[mt], st + 1 * MATB + ra);
            }
#pragma unroll
            for (int ntp = 0; ntp < 2; ntp++) {
                const uint32_t rb = (uint32_t)((wn * 32 + ntp * 16 + b_nsel) * ROWB) + kb + b_koff;
                uint32_t t0[4], t1[4];
                ldmatrix_x4(t0, st + 2 * MATB + rb);
                ldmatrix_x4(t1, st + 3 * MATB + rb);
                b0[ntp * 2 + 0][0] = t0[0]; b0[ntp * 2 + 0][1] = t0[1];
                b0[ntp * 2 + 1][0] = t0[2]; b0[ntp * 2 + 1][1] = t0[3];
                b1[ntp * 2 + 0][0] = t1[0]; b1[ntp * 2 + 0][1] = t1[1];
                b1[ntp * 2 + 1][0] = t1[2]; b1[ntp * 2 + 1][1] = t1[3];
            }

#pragma unroll
            for (int mt = 0; mt < 4; mt++)
#pragma unroll
                for (int nt = 0; nt < 4; nt++) {
                    mma_bf16(d[mt][nt], a0[mt], b1[nt]);
                    mma_bf16(d[mt][nt], a1[mt], b0[nt]);
                    mma_bf16(d[mt][nt], a0[mt], b0[nt]);
                }
        }

        __syncthreads();
        if (kc + 2 < nkc) {
            const uint32_t st2 = sb + (kc & 1) * STAGE3B;
            G3_LOAD(st2, (kc + 2) * 32);
        }
        CP_COMMIT();
    }
#undef G3_LOAD

    const int lrow = lane >> 2;
    const int lcol = (lane & 3) * 2;
#pragma unroll
    for (int mt = 0; mt < 4; mt++) {
#pragma unroll
        for (int nt = 0; nt < 4; nt++) {
            const int row = bm + wm * 64 + mt * 16 + lrow;
            const int col = bn + wn * 32 + nt * 8 + lcol;
            const float bb0 = bias[col], bb1 = bias[col + 1];
            float2 v0 = make_float2(d[mt][nt][0] + bb0, d[mt][nt][1] + bb1);
            float2 v1 = make_float2(d[mt][nt][2] + bb0, d[mt][nt][3] + bb1);
            *(float2*)&C[(size_t)row * N + col] = v0;
            *(float2*)&C[(size_t)(row + 8) * N + col] = v1;
        }
    }
}

// ---------------------------------------------------------------------------
// Batched fp16x2 AV: O[z] = P[z] @ (V0+V1)[z]^T; P single fp16, V fp16 split.
// Tile BM=128, BN=64, BK=32; 256 threads, warps 2x4. grid (LSEQ/128, NPAIR).
// ---------------------------------------------------------------------------
#define AV_AB (128 * ROWB)               // 10240 (single P tile)
#define AV_BB (64 * ROWB)                // 5120
#define AV_STAGE (AV_AB + 2 * AV_BB)     // 20480
#define AV_SMEM_BYTES (2 * AV_STAGE)     // 40960

__global__ __launch_bounds__(256) void av_f16x2(
    const __half* __restrict__ P,
    const __half* __restrict__ V0, const __half* __restrict__ V1,
    __nv_bfloat16* __restrict__ C0, __nv_bfloat16* __restrict__ C1)
{
    extern __shared__ char smem[];
    const uint32_t sb = smem_to_u32(smem);
    const int tid = threadIdx.x;
    const int lane = tid & 31;
    const int wid = tid >> 5;
    const int wm = wid >> 2;
    const int wn = wid & 3;
    const int z = blockIdx.y;
    const int bm = blockIdx.x * 128;
    const __half* Pz = P + (size_t)z * LSEQ * LSEQ;
    const __half* V0z = V0 + (size_t)z * LSEQ * DK;
    const __half* V1z = V1 + (size_t)z * LSEQ * DK;

    float d[4][2][4];
#pragma unroll
    for (int i = 0; i < 4; i++)
#pragma unroll
        for (int j = 0; j < 2; j++)
#pragma unroll
            for (int k = 0; k < 4; k++) d[i][j][k] = 0.f;

#define AV_LOAD(stb, k0)                                                      \
    do {                                                                      \
        _Pragma("unroll")                                                     \
        for (int t = 0; t < 2; t++) {                                         \
            const int idx = tid + t * 256;                                    \
            const int row = idx >> 2, ch = idx & 3;                           \
            const uint32_t off = (uint32_t)(row * ROWB + ch * 16);            \
            const size_t ga = (size_t)(bm + row) * LSEQ + (k0) + ch * 8;      \
            cp_async16((stb) + off, Pz + ga);                                 \
        }                                                                     \
        {                                                                     \
            const int row = tid >> 2, ch = tid & 3;                           \
            if (row < 64) {                                                   \
                const uint32_t off = (uint32_t)(row * ROWB + ch * 16);        \
                const size_t gb = (size_t)row * LSEQ + (k0) + ch * 8;         \
                cp_async16((stb) + AV_AB + off, V0z + gb);                    \
                cp_async16((stb) + AV_AB + AV_BB + off, V1z + gb);            \
            }                                                                 \
        }                                                                     \
    } while (0)

    AV_LOAD(sb, 0);
    CP_COMMIT();
    AV_LOAD(sb + AV_STAGE, 32);
    CP_COMMIT();

    const int a_rowsel = lane & 15;
    const uint32_t a_koff = (uint32_t)((lane >> 4) << 4);
    const int b_nsel = (lane & 7) + ((lane >> 4) << 3);
    const uint32_t b_koff = (uint32_t)(((lane >> 3) & 1) << 4);

    const int nkc = LSEQ / 32;   // 32
    for (int kc = 0; kc < nkc; kc++) {
        if (kc + 1 < nkc) { CP_WAIT(1); } else { CP_WAIT(0); }
        __syncthreads();

        const uint32_t st = sb + (kc & 1) * AV_STAGE;

#pragma unroll
        for (int ks = 0; ks < 2; ks++) {
            const uint32_t kb = ks * 32;

            uint32_t a[4][4];
#pragma unroll
            for (int mt = 0; mt < 4; mt++) {
                const uint32_t ra = (uint32_t)((wm * 64 + mt * 16 + a_rowsel) * ROWB) + kb + a_koff;
                ldmatrix_x4(a[mt], st + ra);
            }
            uint32_t b0[2][2], b1[2][2];
            {
                const uint32_t rb = (uint32_t)((wn * 16 + b_nsel) * ROWB) + kb + b_koff;
                uint32_t t0[4], t1[4];
                ldmatrix_x4(t0, st + AV_AB + rb);
                ldmatrix_x4(t1, st + AV_AB + AV_BB + rb);
                b0[0][0] = t0[0]; b0[0][1] = t0[1];
                b0[1][0] = t0[2]; b0[1][1] = t0[3];
                b1[0][0] = t1[0]; b1[0][1] = t1[1];
                b1[1][0] = t1[2]; b1[1][1] = t1[3];
            }

#pragma unroll
            for (int mt = 0; mt < 4; mt++)
#pragma unroll
                for (int nt = 0; nt < 2; nt++) {
                    mma_f16(d[mt][nt], a[mt], b1[nt]);
                    mma_f16(d[mt][nt], a[mt], b0[nt]);
                }
        }

        __syncthreads();
        if (kc + 2 < nkc) {
            const uint32_t st2 = sb + (kc & 1) * AV_STAGE;
            AV_LOAD(st2, (kc + 2) * 32);
        }
        CP_COMMIT();
    }
#undef AV_LOAD

    const int lrow = lane >> 2;
    const int lcol = (lane & 3) * 2;
#pragma unroll
    for (int mt = 0; mt < 4; mt++) {
#pragma unroll
        for (int nt = 0; nt < 2; nt++) {
            const int row = bm + wm * 64 + mt * 16 + lrow;
            const int col = wn * 16 + nt * 8 + lcol;
            const size_t o0 = (size_t)z * LSEQ * DK + (size_t)row * DK + col;
            const size_t o1 = (size_t)z * LSEQ * DK + (size_t)(row + 8) * DK + col;
            __nv_bfloat16 h0, h1, g0, g1;
            bf16_split2(d[mt][nt][0], h0, h1);
            bf16_split2(d[mt][nt][1], g0, g1);
            *(__nv_bfloat162*)&C0[o0] = __nv_bfloat162(h0, g0);
            *(__nv_bfloat162*)&C1[o0] = __nv_bfloat162(h1, g1);
            bf16_split2(d[mt][nt][2], h0, h1);
            bf16_split2(d[mt][nt][3], g0, g1);
            *(__nv_bfloat162*)&C0[o1] = __nv_bfloat162(h0, g0);
            *(__nv_bfloat162*)&C1[o1] = __nv_bfloat162(h1, g1);
        }
    }
}

// ---------------------------------------------------------------------------
// Launch: R8 structure; softmax emits single-fp16 P; AV uses fp16x2.
// ---------------------------------------------------------------------------
extern "C" void kernel_launch(void* const* d_in, const int* in_sizes, int n_in,
                              void* d_out, int out_size)
{
    const float* x  = (const float*)d_in[0];
    const float* y  = (const float*)d_in[1];
    const float* Wq = (const float*)d_in[2];
    const float* bq = (const float*)d_in[3];
    const float* Wk = (const float*)d_in[4];
    const float* bk = (const float*)d_in[5];
    const float* Wv = (const float*)d_in[6];
    const float* bv = (const float*)d_in[7];
    const float* Wo = (const float*)d_in[8];
    const float* bo = (const float*)d_in[9];
    float* out = (float*)d_out;

    float *gQ, *gK, *gV, *gS;
    cudaGetSymbolAddress((void**)&gQ, g_Q);
    cudaGetSymbolAddress((void**)&gK, g_K);
    cudaGetSymbolAddress((void**)&gV, g_V);
    cudaGetSymbolAddress((void**)&gS, g_S);
    __nv_bfloat16 *y0, *y1, *c0, *c1;
    __nv_bfloat16 *wv0, *wv1, *wo0, *wo1;
    __half *v0t, *v1t, *p;
    cudaGetSymbolAddress((void**)&y0, g_y0);
    cudaGetSymbolAddress((void**)&y1, g_y1);
    cudaGetSymbolAddress((void**)&c0, g_c0);
    cudaGetSymbolAddress((void**)&c1, g_c1);
    cudaGetSymbolAddress((void**)&v0t, g_v0t);
    cudaGetSymbolAddress((void**)&v1t, g_v1t);
    cudaGetSymbolAddress((void**)&p, g_P);
    cudaGetSymbolAddress((void**)&wv0, g_wv0);
    cudaGetSymbolAddress((void**)&wv1, g_wv1);
    cudaGetSymbolAddress((void**)&wo0, g_wo0);
    cudaGetSymbolAddress((void**)&wo1, g_wo1);

    cudaFuncSetAttribute(gemm_bf16x3, cudaFuncAttributeMaxDynamicSharedMemorySize,
                         GEMM3_SMEM_BYTES);
    cudaFuncSetAttribute(av_f16x2, cudaFuncAttributeMaxDynamicSharedMemorySize,
                         AV_SMEM_BYTES);

    cudaEvent_t eFork, eK, eB;
    cudaEventCreateWithFlags(&eFork, cudaEventDisableTiming);
    cudaEventCreateWithFlags(&eK, cudaEventDisableTiming);
    cudaEventCreateWithFlags(&eB, cudaEventDisableTiming);

    const cudaStream_t sMain = 0;                   // legacy default stream
    const cudaStream_t sSide = cudaStreamPerThread; // second lane, no creation

    dim3 tt(32, 8);
    dim3 tg(32, 32);
    dim3 gGemm(D_MODEL / 128, NTOK / 128);  // (8, 64)
    dim3 gScore(LSEQ / 128, LSEQ / 128, NPAIR);
    dim3 gVtG(DK / 32, LSEQ / 32, NPAIR);
    dim3 gAV(LSEQ / 128, NPAIR);
    const int n4 = NTOK * D_MODEL / 4;

    // Fork side lane off the main stream.
    cudaEventRecord(eFork, sMain);
    cudaStreamWaitEvent(sSide, eFork, 0);

    // Side lane: K projection (bit-exact), then the tensor-prep chain.
    sgemm_bias_kernel<<<gGemm, 256, 0, sSide>>>(y, Wk, bk, gK, NTOK, D_MODEL, D_MODEL);
    cudaEventRecord(eK, sSide);
    split2_kernel<<<(n4 + 255) / 256, 256, 0, sSide>>>(y, y0, y1, n4);
    split2_transpose_kernel<<<tg, tt, 0, sSide>>>(Wv, wv0, wv1);
    split2_transpose_kernel<<<tg, tt, 0, sSide>>>(Wo, wo0, wo1);
    gemm_bf16x3<<<gGemm, 256, GEMM3_SMEM_BYTES, sSide>>>(y0, y1, wv0, wv1, bv, gV,
                                                         NTOK, D_MODEL, D_MODEL);
    vt_split_kernel<<<gVtG, tt, 0, sSide>>>(gV, v0t, v1t);
    cudaEventRecord(eB, sSide);

    // Main lane: Q projection runs concurrently with the side lane.
    sgemm_bias_kernel<<<gGemm, 256, 0, sMain>>>(x, Wq, bq, gQ, NTOK, D_MODEL, D_MODEL);

    // Join 1: score needs both Q (main) and K (side).
    cudaStreamWaitEvent(sMain, eK, 0);
    score_kernel<<<gScore, 256, 0, sMain>>>(gQ, gK, gS);
    softmax_kernel<<<(unsigned)(NPAIR * LSEQ), 256, 0, sMain>>>(gS, p);

    // Join 2: AV needs P (main) and split V^T (side).
    cudaStreamWaitEvent(sMain, eB, 0);
    av_f16x2<<<gAV, 256, AV_SMEM_BYTES, sMain>>>(p, v0t, v1t, c0, c1);

    gemm_bf16x3<<<gGemm, 256, GEMM3_SMEM_BYTES, sMain>>>(c0, c1, wo0, wo1, bo, out,
                                                         NTOK, D_MODEL, D_MODEL);
}